// round 2
// baseline (speedup 1.0000x reference)
#include <cuda_runtime.h>
#include <math.h>

#define NQ    16
#define DIMN  65536
#define BATCH 64
#define NCLS  23

// ---------------- device scratch ----------------
__device__ float2 g_state[BATCH][DIMN];   // 32 MB
__device__ float2 g_v1[BATCH][NQ][2];     // layer-1 fused (Rot*RX)|0> columns
__device__ float2 g_U2[BATCH][NQ][4];     // layer-2 fused Rot*RX matrices
__device__ float2 g_prefix[BATCH][16];    // entangled prefix over wires 0..3
__device__ float2 g_crx1[NQ];             // (cos th/2, sin th/2)
__device__ float2 g_crx2[NQ];
__device__ float  g_feats[BATCH][NQ];

// ---------------- helpers ----------------
__device__ __forceinline__ float2 cmul(float2 a, float2 b) {
    return make_float2(a.x*b.x - a.y*b.y, a.x*b.y + a.y*b.x);
}
// RX mix on (t0,t1) with k=(cos,sin):  t0' = c t0 - i s t1 ; t1' = c t1 - i s t0
__device__ __forceinline__ void crxmix(float2& t0, float2& t1, float2 k) {
    float c = k.x, s = k.y;
    float2 n0 = make_float2(c*t0.x + s*t1.y, c*t0.y - s*t1.x);
    float2 n1 = make_float2(c*t1.x + s*t0.y, c*t1.y - s*t0.x);
    t0 = n0; t1 = n1;
}
__device__ __forceinline__ void apU(float2& a0, float2& a1,
                                    float2 u00, float2 u01, float2 u10, float2 u11) {
    float2 n0 = make_float2(u00.x*a0.x - u00.y*a0.y + u01.x*a1.x - u01.y*a1.y,
                            u00.x*a0.y + u00.y*a0.x + u01.x*a1.y + u01.y*a1.x);
    float2 n1 = make_float2(u10.x*a0.x - u10.y*a0.y + u11.x*a1.x - u11.y*a1.y,
                            u10.x*a0.y + u10.y*a0.x + u11.x*a1.y + u11.y*a1.x);
    a0 = n0; a1 = n1;
}
// a[8], i = (ba<<2)|(bb<<1)|bc for wires (wa,wb,wc)
__device__ __forceinline__ void apU_wb(float2* a, const float2* U) {
    float2 u0=U[0],u1=U[1],u2=U[2],u3=U[3];
    apU(a[0],a[2],u0,u1,u2,u3); apU(a[1],a[3],u0,u1,u2,u3);
    apU(a[4],a[6],u0,u1,u2,u3); apU(a[5],a[7],u0,u1,u2,u3);
}
__device__ __forceinline__ void apU_wc(float2* a, const float2* U) {
    float2 u0=U[0],u1=U[1],u2=U[2],u3=U[3];
    apU(a[0],a[1],u0,u1,u2,u3); apU(a[2],a[3],u0,u1,u2,u3);
    apU(a[4],a[5],u0,u1,u2,u3); apU(a[6],a[7],u0,u1,u2,u3);
}
__device__ __forceinline__ void crx_ab(float2* a, float2 k) {  // ctrl wa, tgt wb
    crxmix(a[4], a[6], k); crxmix(a[5], a[7], k);
}
__device__ __forceinline__ void crx_bc(float2* a, float2 k) {  // ctrl wb, tgt wc
    crxmix(a[2], a[3], k); crxmix(a[6], a[7], k);
}
#define SWZ(e) ((e) ^ (((e) >> 4) & 0xF))

template<int P0, int P1, int P2>
__device__ __forceinline__ int expand3(int t) {
    t = ((t >> P0) << (P0 + 1)) | (t & ((1 << P0) - 1));
    t = ((t >> P1) << (P1 + 1)) | (t & ((1 << P1) - 1));
    t = ((t >> P2) << (P2 + 1)) | (t & ((1 << P2) - 1));
    return t;
}
template<int PA, int PB, int PC>
__device__ __forceinline__ void sld(const float2* st, int base, float2* a) {
#pragma unroll
    for (int i = 0; i < 8; i++) {
        int idx = base | (((i >> 2) & 1) << PA) | (((i >> 1) & 1) << PB) | ((i & 1) << PC);
        a[i] = st[SWZ(idx)];
    }
}
template<int PA, int PB, int PC>
__device__ __forceinline__ void sst(float2* st, int base, const float2* a) {
#pragma unroll
    for (int i = 0; i < 8; i++) {
        int idx = base | (((i >> 2) & 1) << PA) | (((i >> 1) & 1) << PB) | ((i & 1) << PC);
        st[SWZ(idx)] = a[i];
    }
}

// fused U = Rot(phi,theta,omega) * RX(xv); out[4] = {U00,U01,U10,U11}
__device__ __forceinline__ void fuse_rot_rx(float phi, float th, float om, float xv, float2* out) {
    float sx, cx; sincosf(0.5f * xv, &sx, &cx);
    float st, ct; sincosf(0.5f * th, &st, &ct);
    float sa, ca; sincosf(0.5f * (phi + om), &sa, &ca);
    float sb, cb; sincosf(0.5f * (phi - om), &sb, &cb);
    float2 A = make_float2( ca*ct, -sa*ct);
    float2 B = make_float2(-cb*st, -sb*st);
    float2 C = make_float2( cb*st, -sb*st);
    float2 D = make_float2( ca*ct,  sa*ct);
    out[0] = make_float2(A.x*cx + B.y*sx,  A.y*cx - B.x*sx);
    out[1] = make_float2(A.y*sx + B.x*cx, -A.x*sx + B.y*cx);
    out[2] = make_float2(C.x*cx + D.y*sx,  C.y*cx - D.x*sx);
    out[3] = make_float2(C.y*sx + D.x*cx, -C.x*sx + D.y*cx);
}

// ---------------- prep ----------------
__global__ void k_prep(const float* __restrict__ x,  const float* __restrict__ w0,
                       const float* __restrict__ x0, const float* __restrict__ w1,
                       const float* __restrict__ x1) {
    int b = threadIdx.x;
    if (b >= BATCH) return;
    float2 v[4][2];
    for (int q = 0; q < NQ; q++) {
        float xv = x[b * NQ + q];
        float2 U[4];
        fuse_rot_rx(w0[q*3+0], w0[q*3+1], w0[q*3+2], xv, U);   // layer 1
        g_v1[b][q][0] = U[0]; g_v1[b][q][1] = U[2];            // column 0
        if (q < 4) { v[q][0] = U[0]; v[q][1] = U[2]; }
        fuse_rot_rx(w1[q*3+0], w1[q*3+1], w1[q*3+2], xv, U);   // layer 2
        g_U2[b][q][0] = U[0]; g_U2[b][q][1] = U[1];
        g_U2[b][q][2] = U[2]; g_U2[b][q][3] = U[3];
    }
    if (b == 0) {
        for (int q = 0; q < NQ; q++) {
            float s, c;
            sincosf(0.5f * x0[q], &s, &c); g_crx1[q] = make_float2(c, s);
            sincosf(0.5f * x1[q], &s, &c); g_crx2[q] = make_float2(c, s);
        }
    }
    // prefix over wires 0..3 (index j = b0b1b2b3), apply CRX(0,1),(1,2),(2,3)
    float2 amp[16];
#pragma unroll
    for (int j = 0; j < 16; j++) {
        int b0=(j>>3)&1, b1=(j>>2)&1, b2=(j>>1)&1, b3=j&1;
        amp[j] = cmul(cmul(v[0][b0], v[1][b1]), cmul(v[2][b2], v[3][b3]));
    }
    float s, c;
    sincosf(0.5f * x0[0], &s, &c); { float2 k = make_float2(c, s);
        crxmix(amp[8],amp[12],k);  crxmix(amp[9],amp[13],k);
        crxmix(amp[10],amp[14],k); crxmix(amp[11],amp[15],k); }
    sincosf(0.5f * x0[1], &s, &c); { float2 k = make_float2(c, s);
        crxmix(amp[4],amp[6],k);   crxmix(amp[5],amp[7],k);
        crxmix(amp[12],amp[14],k); crxmix(amp[13],amp[15],k); }
    sincosf(0.5f * x0[2], &s, &c); { float2 k = make_float2(c, s);
        crxmix(amp[2],amp[3],k);   crxmix(amp[6],amp[7],k);
        crxmix(amp[10],amp[11],k); crxmix(amp[14],amp[15],k); }
#pragma unroll
    for (int j = 0; j < 16; j++) g_prefix[b][j] = amp[j];
#pragma unroll
    for (int w = 0; w < NQ; w++) g_feats[b][w] = 0.f;
}

// ---------------- pass 1: build state + layer1 CRX(3,4)..(14,15) ----------------
// slab = wires 0..3 = global bits 15..12 ; local l = bits 11..0 = wires 4..15
__global__ void __launch_bounds__(512) k_pass1() {
    __shared__ float2 st[4096];
    int slab = blockIdx.x, b = blockIdx.y, tid = threadIdx.x;
    // g1: wires (4,5,6) = bits (11,10,9): construct; CRX(4,5),(5,6)
    {
        int base = expand3<9,10,11>(tid);
        float2 common = g_v1[b][7][(base >> 8) & 1];
#pragma unroll
        for (int q = 8; q < 16; q++) common = cmul(common, g_v1[b][q][(base >> (15 - q)) & 1]);
        common = cmul(common, g_prefix[b][slab]);
        float2 v40 = g_v1[b][4][0], v41 = g_v1[b][4][1];
        if (slab & 1) crxmix(v40, v41, g_crx1[3]);   // CRX(3,4): ctrl wire3 = slab bit0
        float2 v50 = g_v1[b][5][0], v51 = g_v1[b][5][1];
        float2 v60 = g_v1[b][6][0], v61 = g_v1[b][6][1];
        float2 a[8];
#pragma unroll
        for (int i = 0; i < 8; i++) {
            float2 t = cmul(((i >> 2) & 1) ? v41 : v40, ((i >> 1) & 1) ? v51 : v50);
            a[i] = cmul(cmul(t, (i & 1) ? v61 : v60), common);
        }
        crx_ab(a, g_crx1[4]); crx_bc(a, g_crx1[5]);
        sst<11,10,9>(st, base, a);
    }
    __syncthreads();
    { float2 a[8]; int base = expand3<7,8,9>(tid);
      sld<9,8,7>(st, base, a); crx_ab(a, g_crx1[6]);  crx_bc(a, g_crx1[7]);  sst<9,8,7>(st, base, a); }
    __syncthreads();
    { float2 a[8]; int base = expand3<5,6,7>(tid);
      sld<7,6,5>(st, base, a); crx_ab(a, g_crx1[8]);  crx_bc(a, g_crx1[9]);  sst<7,6,5>(st, base, a); }
    __syncthreads();
    { float2 a[8]; int base = expand3<3,4,5>(tid);
      sld<5,4,3>(st, base, a); crx_ab(a, g_crx1[10]); crx_bc(a, g_crx1[11]); sst<5,4,3>(st, base, a); }
    __syncthreads();
    { float2 a[8]; int base = expand3<1,2,3>(tid);
      sld<3,2,1>(st, base, a); crx_ab(a, g_crx1[12]); crx_bc(a, g_crx1[13]); sst<3,2,1>(st, base, a); }
    __syncthreads();
    {   // wires (13,14,15) = bits (2,1,0): CRX(14,15); write out
        float2 a[8]; int base = tid << 3;
        sld<2,1,0>(st, base, a);
        crx_bc(a, g_crx1[14]);
        float2* out = &g_state[b][(slab << 12) | base];
#pragma unroll
        for (int i = 0; i < 8; i++) out[i] = a[i];
    }
}

// ---------------- pass B: slab bits = wires 6..9 (global bits 9..6) ----------------
// l bits 11..6 = wires 0..5 (global 15..10); l bits 5..0 = wires 10..15 (global 5..0)
__device__ __forceinline__ int mapB(int l, int slab) {
    return ((l >> 6) << 10) | (slab << 6) | (l & 0x3F);
}
__global__ void __launch_bounds__(512) k_passB() {
    __shared__ float2 st[4096];
    int slab = blockIdx.x, b = blockIdx.y, tid = threadIdx.x;
    // b1: wires (15,0,1) = bits (0,11,10): CRX(15,0)L1; U0; U1; CRX(0,1)L2
    {
        float2 a[8]; int base = expand3<0,10,11>(tid);
#pragma unroll
        for (int i = 0; i < 8; i++) {
            int l = base | ((i >> 2) & 1) | (((i >> 1) & 1) << 11) | ((i & 1) << 10);
            a[i] = g_state[b][mapB(l, slab)];
        }
        crx_ab(a, g_crx1[15]);
        apU_wb(a, g_U2[b][0]); apU_wc(a, g_U2[b][1]);
        crx_bc(a, g_crx2[0]);
        sst<0,11,10>(st, base, a);
    }
    __syncthreads();
    // b2: wires (1,2,3) = bits (10,9,8): U2; U3; CRX(1,2); CRX(2,3)
    { float2 a[8]; int base = expand3<8,9,10>(tid);
      sld<10,9,8>(st, base, a);
      apU_wb(a, g_U2[b][2]); apU_wc(a, g_U2[b][3]);
      crx_ab(a, g_crx2[1]);  crx_bc(a, g_crx2[2]);
      sst<10,9,8>(st, base, a); }
    __syncthreads();
    // b3: wires (3,4,5) = bits (8,7,6): U4; U5; CRX(3,4); CRX(4,5); store
    {
        float2 a[8]; int base = expand3<6,7,8>(tid);
        sld<8,7,6>(st, base, a);
        apU_wb(a, g_U2[b][4]); apU_wc(a, g_U2[b][5]);
        crx_ab(a, g_crx2[3]);  crx_bc(a, g_crx2[4]);
#pragma unroll
        for (int i = 0; i < 8; i++) {
            int l = base | (((i >> 2) & 1) << 8) | (((i >> 1) & 1) << 7) | ((i & 1) << 6);
            g_state[b][mapB(l, slab)] = a[i];
        }
    }
}

// ---------------- pass C: slab bits = wires 0..3; gates U6..U15, CRX(5,6)..(14,15) ----
__global__ void __launch_bounds__(512) k_passC() {
    __shared__ float2 st[4096];
    int slab = blockIdx.x, b = blockIdx.y, tid = threadIdx.x;
    // c1: wires (5,6,7) = bits (10,9,8): U6; U7; CRX(5,6); CRX(6,7)
    {
        float2 a[8]; int base = expand3<8,9,10>(tid);
        const float2* g = &g_state[b][slab << 12];
#pragma unroll
        for (int i = 0; i < 8; i++) {
            int l = base | (((i >> 2) & 1) << 10) | (((i >> 1) & 1) << 9) | ((i & 1) << 8);
            a[i] = g[l];
        }
        apU_wb(a, g_U2[b][6]); apU_wc(a, g_U2[b][7]);
        crx_ab(a, g_crx2[5]);  crx_bc(a, g_crx2[6]);
        sst<10,9,8>(st, base, a);
    }
    __syncthreads();
    { float2 a[8]; int base = expand3<6,7,8>(tid);     // wires (7,8,9)
      sld<8,7,6>(st, base, a);
      apU_wb(a, g_U2[b][8]); apU_wc(a, g_U2[b][9]);
      crx_ab(a, g_crx2[7]);  crx_bc(a, g_crx2[8]);
      sst<8,7,6>(st, base, a); }
    __syncthreads();
    { float2 a[8]; int base = expand3<4,5,6>(tid);     // wires (9,10,11)
      sld<6,5,4>(st, base, a);
      apU_wb(a, g_U2[b][10]); apU_wc(a, g_U2[b][11]);
      crx_ab(a, g_crx2[9]);   crx_bc(a, g_crx2[10]);
      sst<6,5,4>(st, base, a); }
    __syncthreads();
    { float2 a[8]; int base = expand3<2,3,4>(tid);     // wires (11,12,13)
      sld<4,3,2>(st, base, a);
      apU_wb(a, g_U2[b][12]); apU_wc(a, g_U2[b][13]);
      crx_ab(a, g_crx2[11]);  crx_bc(a, g_crx2[12]);
      sst<4,3,2>(st, base, a); }
    __syncthreads();
    {   // wires (13,14,15) = bits (2,1,0): U14; U15; CRX(13,14); CRX(14,15); store
        float2 a[8]; int base = tid << 3;
        sld<2,1,0>(st, base, a);
        apU_wb(a, g_U2[b][14]); apU_wc(a, g_U2[b][15]);
        crx_ab(a, g_crx2[13]);  crx_bc(a, g_crx2[14]);
        float2* out = &g_state[b][(slab << 12) | base];
#pragma unroll
        for (int i = 0; i < 8; i++) out[i] = a[i];
    }
}

// ---------------- expvals: fuse CRX(15,0)L2 + |amp|^2 + PauliZ sums ----------------
__global__ void __launch_bounds__(256) k_expval() {
    __shared__ float red[16];
    int b = blockIdx.y;
    int tg = blockIdx.x * 256 + threadIdx.x;      // [0, 2048)
    int base = tg << 4;                           // 16 amps, msb=0
    float2 k = g_crx2[15];                        // ctrl wire15(lsb), tgt wire0(msb)
    const float4* pA = (const float4*)&g_state[b][base];
    const float4* pB = (const float4*)&g_state[b][base + 32768];
    float TA = 0.f, TB = 0.f, ZL0 = 0.f, ZL1 = 0.f, ZL2 = 0.f, ZL3 = 0.f;
#pragma unroll
    for (int i = 0; i < 16; i += 2) {
        float4 av = pA[i >> 1], bv = pB[i >> 1];
        float2 a0 = make_float2(av.x, av.y), a1 = make_float2(av.z, av.w);
        float2 b0 = make_float2(bv.x, bv.y), b1 = make_float2(bv.z, bv.w);
        crxmix(a1, b1, k);                        // lsb=1 amps mix across msb
        float pa0 = a0.x*a0.x + a0.y*a0.y, pa1 = a1.x*a1.x + a1.y*a1.y;
        float pb0 = b0.x*b0.x + b0.y*b0.y, pb1 = b1.x*b1.x + b1.y*b1.y;
        float ps0 = pa0 + pb0, ps1 = pa1 + pb1;
        TA += pa0 + pa1;  TB += pb0 + pb1;
        ZL0 += ps0 - ps1;
        ZL1 += ((i >> 1) & 1) ? -(ps0 + ps1) : (ps0 + ps1);
        ZL2 += ((i >> 2) & 1) ? -(ps0 + ps1) : (ps0 + ps1);
        ZL3 += ((i >> 3) & 1) ? -(ps0 + ps1) : (ps0 + ps1);
    }
    float z[16];
    z[0] = TA - TB;
    float T = TA + TB;
#pragma unroll
    for (int w = 1; w < 12; w++)
        z[w] = ((base >> (15 - w)) & 1) ? -T : T;
    z[12] = ZL3; z[13] = ZL2; z[14] = ZL1; z[15] = ZL0;
    if (threadIdx.x < 16) red[threadIdx.x] = 0.f;
    __syncthreads();
#pragma unroll
    for (int w = 0; w < 16; w++) {
#pragma unroll
        for (int o = 16; o > 0; o >>= 1) z[w] += __shfl_xor_sync(0xFFFFFFFFu, z[w], o);
    }
    if ((threadIdx.x & 31) == 0)
#pragma unroll
        for (int w = 0; w < 16; w++) atomicAdd(&red[w], z[w]);
    __syncthreads();
    if (threadIdx.x < 16) atomicAdd(&g_feats[b][threadIdx.x], red[threadIdx.x]);
}

// ---------------- FC + log_softmax ----------------
__global__ void k_fc(const float* __restrict__ fc_w, const float* __restrict__ fc_b,
                     float* __restrict__ out) {
    int b = threadIdx.x;
    if (b >= BATCH) return;
    float f[16];
#pragma unroll
    for (int w = 0; w < 16; w++) f[w] = g_feats[b][w];
    float l[NCLS], m = -1e30f;
    for (int c = 0; c < NCLS; c++) {
        float s = fc_b[c];
#pragma unroll
        for (int w = 0; w < 16; w++) s += f[w] * fc_w[c * 16 + w];
        l[c] = s; m = fmaxf(m, s);
    }
    float se = 0.f;
    for (int c = 0; c < NCLS; c++) se += expf(l[c] - m);
    float lse = m + logf(se);
    for (int c = 0; c < NCLS; c++) out[b * NCLS + c] = l[c] - lse;
}

extern "C" void kernel_launch(void* const* d_in, const int* in_sizes, int n_in,
                              void* d_out, int out_size) {
    const float* x    = (const float*)d_in[0];
    const float* w0   = (const float*)d_in[1];
    const float* x0   = (const float*)d_in[2];
    const float* w1   = (const float*)d_in[3];
    const float* x1   = (const float*)d_in[4];
    const float* fc_w = (const float*)d_in[5];
    const float* fc_b = (const float*)d_in[6];
    float* out = (float*)d_out;

    k_prep<<<1, 64>>>(x, w0, x0, w1, x1);
    dim3 grid(16, BATCH);
    k_pass1<<<grid, 512>>>();
    k_passB<<<grid, 512>>>();
    k_passC<<<grid, 512>>>();
    k_expval<<<dim3(8, BATCH), 256>>>();
    k_fc<<<1, 64>>>(fc_w, fc_b, out);
}

// round 5
// speedup vs baseline: 1.4875x; 1.4875x over previous
#include <cuda_runtime.h>
#include <math.h>

#define NQ    16
#define DIMN  65536
#define BATCH 64
#define NCLS  23

// ---------------- device scratch ----------------
__device__ float2 g_state[BATCH][DIMN];   // 32 MB
__device__ float2 g_v1[BATCH][NQ][2];     // layer-1 fused (Rot*RX)|0> columns
__device__ float2 g_U2[BATCH][NQ][4];     // layer-2 fused Rot*RX matrices
__device__ float2 g_prefix[BATCH][16];    // entangled prefix over wires 0..3
__device__ float2 g_crx1[NQ];             // (cos th/2, sin th/2)
__device__ float2 g_crx2[NQ];
__device__ float  g_feats[BATCH][NQ];

// ---------------- helpers ----------------
__device__ __forceinline__ float2 cmul(float2 a, float2 b) {
    return make_float2(a.x*b.x - a.y*b.y, a.x*b.y + a.y*b.x);
}
// RX mix: t0' = c t0 - i s t1 ; t1' = c t1 - i s t0,  k=(c,s)
__device__ __forceinline__ void crxmix(float2& t0, float2& t1, float2 k) {
    float c = k.x, s = k.y;
    float2 n0 = make_float2(c*t0.x + s*t1.y, c*t0.y - s*t1.x);
    float2 n1 = make_float2(c*t1.x + s*t0.y, c*t1.y - s*t0.x);
    t0 = n0; t1 = n1;
}
__device__ __forceinline__ void apU(float2& a0, float2& a1,
                                    float2 u00, float2 u01, float2 u10, float2 u11) {
    float2 n0 = make_float2(u00.x*a0.x - u00.y*a0.y + u01.x*a1.x - u01.y*a1.y,
                            u00.x*a0.y + u00.y*a0.x + u01.x*a1.y + u01.y*a1.x);
    float2 n1 = make_float2(u10.x*a0.x - u10.y*a0.y + u11.x*a1.x - u11.y*a1.y,
                            u10.x*a0.y + u10.y*a0.x + u11.x*a1.y + u11.y*a1.x);
    a0 = n0; a1 = n1;
}
// 16-amp register tile, amp index i = (b3<<3)|(b2<<2)|(b1<<1)|b0
template<int B>
__device__ __forceinline__ void apU16(float2* a, const float2* U) {
    float2 u0 = U[0], u1 = U[1], u2 = U[2], u3 = U[3];
#pragma unroll
    for (int i = 0; i < 16; i++)
        if (!((i >> B) & 1)) apU(a[i], a[i | (1 << B)], u0, u1, u2, u3);
}
template<int CB, int TB>
__device__ __forceinline__ void crx16(float2* a, float2 k) {
#pragma unroll
    for (int i = 0; i < 16; i++)
        if (((i >> CB) & 1) && !((i >> TB) & 1)) crxmix(a[i], a[i | (1 << TB)], k);
}
#define SWZ(e) ((e) ^ (((e) >> 4) & 0xF))

template<int P0, int P1, int P2, int P3>   // ascending insert positions
__device__ __forceinline__ int expand4(int t) {
    t = ((t >> P0) << (P0 + 1)) | (t & ((1 << P0) - 1));
    t = ((t >> P1) << (P1 + 1)) | (t & ((1 << P1) - 1));
    t = ((t >> P2) << (P2 + 1)) | (t & ((1 << P2) - 1));
    t = ((t >> P3) << (P3 + 1)) | (t & ((1 << P3) - 1));
    return t;
}
// bit3->PA, bit2->PB, bit1->PC, bit0->PD
template<int PA, int PB, int PC, int PD>
__device__ __forceinline__ void sld16(const float2* st, int base, float2* a) {
#pragma unroll
    for (int i = 0; i < 16; i++) {
        int idx = base | (((i>>3)&1)<<PA) | (((i>>2)&1)<<PB) | (((i>>1)&1)<<PC) | ((i&1)<<PD);
        a[i] = st[SWZ(idx)];
    }
}
template<int PA, int PB, int PC, int PD>
__device__ __forceinline__ void sst16(float2* st, int base, const float2* a) {
#pragma unroll
    for (int i = 0; i < 16; i++) {
        int idx = base | (((i>>3)&1)<<PA) | (((i>>2)&1)<<PB) | (((i>>1)&1)<<PC) | ((i&1)<<PD);
        st[SWZ(idx)] = a[i];
    }
}

// fused U = Rot(phi,theta,omega) * RX(xv); out[4] = {U00,U01,U10,U11}
__device__ __forceinline__ void fuse_rot_rx(float phi, float th, float om, float xv, float2* out) {
    float sx, cx; sincosf(0.5f * xv, &sx, &cx);
    float st, ct; sincosf(0.5f * th, &st, &ct);
    float sa, ca; sincosf(0.5f * (phi + om), &sa, &ca);
    float sb, cb; sincosf(0.5f * (phi - om), &sb, &cb);
    float2 A = make_float2( ca*ct, -sa*ct);
    float2 B = make_float2(-cb*st, -sb*st);
    float2 C = make_float2( cb*st, -sb*st);
    float2 D = make_float2( ca*ct,  sa*ct);
    out[0] = make_float2(A.x*cx + B.y*sx,  A.y*cx - B.x*sx);
    out[1] = make_float2(A.y*sx + B.x*cx, -A.x*sx + B.y*cx);
    out[2] = make_float2(C.x*cx + D.y*sx,  C.y*cx - D.x*sx);
    out[3] = make_float2(C.y*sx + D.x*cx, -C.x*sx + D.y*cx);
}

// ---------------- prep ----------------
__global__ void k_prep(const float* __restrict__ x,  const float* __restrict__ w0,
                       const float* __restrict__ x0, const float* __restrict__ w1,
                       const float* __restrict__ x1) {
    int b = threadIdx.x;
    if (b >= BATCH) return;
    float2 v[4][2];
    for (int q = 0; q < NQ; q++) {
        float xv = x[b * NQ + q];
        float2 U[4];
        fuse_rot_rx(w0[q*3+0], w0[q*3+1], w0[q*3+2], xv, U);   // layer 1
        g_v1[b][q][0] = U[0]; g_v1[b][q][1] = U[2];            // column 0
        if (q < 4) { v[q][0] = U[0]; v[q][1] = U[2]; }
        fuse_rot_rx(w1[q*3+0], w1[q*3+1], w1[q*3+2], xv, U);   // layer 2
        g_U2[b][q][0] = U[0]; g_U2[b][q][1] = U[1];
        g_U2[b][q][2] = U[2]; g_U2[b][q][3] = U[3];
    }
    if (b == 0) {
        for (int q = 0; q < NQ; q++) {
            float s, c;
            sincosf(0.5f * x0[q], &s, &c); g_crx1[q] = make_float2(c, s);
            sincosf(0.5f * x1[q], &s, &c); g_crx2[q] = make_float2(c, s);
        }
    }
    // prefix over wires 0..3 (j = b0 b1 b2 b3), CRX(0,1),(1,2),(2,3)
    float2 amp[16];
#pragma unroll
    for (int j = 0; j < 16; j++) {
        int b0=(j>>3)&1, b1=(j>>2)&1, b2=(j>>1)&1, b3=j&1;
        amp[j] = cmul(cmul(v[0][b0], v[1][b1]), cmul(v[2][b2], v[3][b3]));
    }
    float s, c;
    sincosf(0.5f * x0[0], &s, &c); { float2 k = make_float2(c, s);
        crxmix(amp[8],amp[12],k);  crxmix(amp[9],amp[13],k);
        crxmix(amp[10],amp[14],k); crxmix(amp[11],amp[15],k); }
    sincosf(0.5f * x0[1], &s, &c); { float2 k = make_float2(c, s);
        crxmix(amp[4],amp[6],k);   crxmix(amp[5],amp[7],k);
        crxmix(amp[12],amp[14],k); crxmix(amp[13],amp[15],k); }
    sincosf(0.5f * x0[2], &s, &c); { float2 k = make_float2(c, s);
        crxmix(amp[2],amp[3],k);   crxmix(amp[6],amp[7],k);
        crxmix(amp[10],amp[11],k); crxmix(amp[14],amp[15],k); }
#pragma unroll
    for (int j = 0; j < 16; j++) g_prefix[b][j] = amp[j];
#pragma unroll
    for (int w = 0; w < NQ; w++) g_feats[b][w] = 0.f;
}

// ---------------- pass1: build state + L1 CRX(3,4)..(14,15) -----------------
// slab = wires 0..3 (global bits 15..12); local l bits 11..0 = wires 4..15
__global__ void __launch_bounds__(256) k_pass1() {
    __shared__ float2 st[4096];
    int slab = blockIdx.x, b = blockIdx.y, tid = threadIdx.x;
    // g1: wires (4,5,6,7) = l bits (11,10,9,8): construct; fold CRX(3,4); CRX(4,5),(5,6),(6,7)
    {
        int base = expand4<8,9,10,11>(tid);           // tid[7:0] -> l[7:0]
        float2 common = g_prefix[b][slab];
#pragma unroll
        for (int q = 8; q < 16; q++) common = cmul(common, g_v1[b][q][(base >> (15 - q)) & 1]);
        float2 v40 = g_v1[b][4][0], v41 = g_v1[b][4][1];
        if (slab & 1) crxmix(v40, v41, g_crx1[3]);    // ctrl wire3 = slab bit0
        float2 v50 = g_v1[b][5][0], v51 = g_v1[b][5][1];
        float2 v60 = g_v1[b][6][0], v61 = g_v1[b][6][1];
        float2 v70 = g_v1[b][7][0], v71 = g_v1[b][7][1];
        float2 t45[4], t67[4];
        t45[0]=cmul(v40,v50); t45[1]=cmul(v40,v51); t45[2]=cmul(v41,v50); t45[3]=cmul(v41,v51);
        t67[0]=cmul(v60,v70); t67[1]=cmul(v60,v71); t67[2]=cmul(v61,v70); t67[3]=cmul(v61,v71);
        float2 a[16];
#pragma unroll
        for (int i = 0; i < 16; i++) a[i] = cmul(cmul(t45[i >> 2], t67[i & 3]), common);
        crx16<3,2>(a, g_crx1[4]);
        crx16<2,1>(a, g_crx1[5]);
        crx16<1,0>(a, g_crx1[6]);
        sst16<11,10,9,8>(st, base, a);
    }
    __syncthreads();
    { float2 a[16]; int base = expand4<5,6,7,8>(tid);   // wires (7,8,9,10)
      sld16<8,7,6,5>(st, base, a);
      crx16<3,2>(a, g_crx1[7]); crx16<2,1>(a, g_crx1[8]); crx16<1,0>(a, g_crx1[9]);
      sst16<8,7,6,5>(st, base, a); }
    __syncthreads();
    { float2 a[16]; int base = expand4<2,3,4,5>(tid);   // wires (10,11,12,13)
      sld16<5,4,3,2>(st, base, a);
      crx16<3,2>(a, g_crx1[10]); crx16<2,1>(a, g_crx1[11]); crx16<1,0>(a, g_crx1[12]);
      sst16<5,4,3,2>(st, base, a); }
    __syncthreads();
    {   // wires (12,13,14,15) = bits (3,2,1,0): CRX(13,14),(14,15); write out
        float2 a[16]; int base = tid << 4;
        sld16<3,2,1,0>(st, base, a);
        crx16<2,1>(a, g_crx1[13]); crx16<1,0>(a, g_crx1[14]);
        float4* out = (float4*)&g_state[b][(slab << 12) | base];
#pragma unroll
        for (int j = 0; j < 8; j++)
            out[j] = make_float4(a[2*j].x, a[2*j].y, a[2*j+1].x, a[2*j+1].y);
    }
}

// ---------------- passB: slab = wires 6..9 (global bits 9..6) ----------------
// l bits 11..6 = wires 0..5 (global 15..10); l bits 5..0 = wires 10..15 (global 5..0)
__device__ __forceinline__ int mapB(int l, int s) {
    return ((l >> 6) << 10) | (s << 6) | (l & 0x3F);
}
__global__ void __launch_bounds__(256) k_passB() {
    __shared__ float2 st[4096];
    int slab = blockIdx.x, b = blockIdx.y, tid = threadIdx.x;
    // g1: wires (15,0,1,2) = l bits (0,11,10,9): CRX(15,0)L1; U0;U1;U2; CRX(0,1),(1,2)
    {
        float2 a[16];
        int base = expand4<0,9,10,11>(tid);           // tid[7:0] -> l[8:1]
#pragma unroll
        for (int j = 0; j < 8; j++) {                 // pair (j, j|8) adjacent (l bit0)
            int lo = base | (((j>>2)&1)<<11) | (((j>>1)&1)<<10) | ((j&1)<<9);
            float4 v = *(const float4*)&g_state[b][mapB(lo, slab)];
            a[j]     = make_float2(v.x, v.y);
            a[j | 8] = make_float2(v.z, v.w);
        }
        crx16<3,2>(a, g_crx1[15]);
        apU16<2>(a, g_U2[b][0]); apU16<1>(a, g_U2[b][1]); apU16<0>(a, g_U2[b][2]);
        crx16<2,1>(a, g_crx2[0]); crx16<1,0>(a, g_crx2[1]);
        sst16<0,11,10,9>(st, base, a);
    }
    __syncthreads();
    // g2: wires (2,3,4,5) = l bits (9,8,7,6): U3;U4;U5; CRX(2,3),(3,4),(4,5); store
    {
        float2 a[16]; int base = expand4<6,7,8,9>(tid);
        sld16<9,8,7,6>(st, base, a);
        apU16<2>(a, g_U2[b][3]); apU16<1>(a, g_U2[b][4]); apU16<0>(a, g_U2[b][5]);
        crx16<3,2>(a, g_crx2[2]); crx16<2,1>(a, g_crx2[3]); crx16<1,0>(a, g_crx2[4]);
#pragma unroll
        for (int i = 0; i < 16; i++) {
            int l = base | (((i>>3)&1)<<9) | (((i>>2)&1)<<8) | (((i>>1)&1)<<7) | ((i&1)<<6);
            g_state[b][mapB(l, slab)] = a[i];
        }
    }
}

// ---------------- passC: slab = wires 1..4 (global bits 14..11) --------------
// l bit 11 = wire 0 (global bit 15); l bits 10..0 = wires 5..15 (global 10..0)
// gates U6..U15, CRX(5,6)..(14,15),(15,0) L2, fused measurement. READ-ONLY.
__device__ __forceinline__ int mapC(int l, int s) {
    return ((l >> 11) << 15) | (s << 11) | (l & 0x7FF);
}
__global__ void __launch_bounds__(256) k_passC() {
    __shared__ float2 st[4096];
    __shared__ float red[16];
    int slab = blockIdx.x, b = blockIdx.y, tid = threadIdx.x;
    if (tid < 16) red[tid] = 0.f;
    // g1: wires (5,6,7,8) = l bits (10,9,8,7): U6;U7;U8; CRX(5,6),(6,7),(7,8)
    {
        float2 a[16]; int base = expand4<7,8,9,10>(tid);   // tid[6:0]->l[6:0], tid7->l11
#pragma unroll
        for (int i = 0; i < 16; i++) {
            int l = base | (((i>>3)&1)<<10) | (((i>>2)&1)<<9) | (((i>>1)&1)<<8) | ((i&1)<<7);
            a[i] = g_state[b][mapC(l, slab)];
        }
        apU16<2>(a, g_U2[b][6]); apU16<1>(a, g_U2[b][7]); apU16<0>(a, g_U2[b][8]);
        crx16<3,2>(a, g_crx2[5]); crx16<2,1>(a, g_crx2[6]); crx16<1,0>(a, g_crx2[7]);
        sst16<10,9,8,7>(st, base, a);
    }
    __syncthreads();
    { float2 a[16]; int base = expand4<4,5,6,7>(tid);      // wires (8,9,10,11)
      sld16<7,6,5,4>(st, base, a);
      apU16<2>(a, g_U2[b][9]); apU16<1>(a, g_U2[b][10]); apU16<0>(a, g_U2[b][11]);
      crx16<3,2>(a, g_crx2[8]); crx16<2,1>(a, g_crx2[9]); crx16<1,0>(a, g_crx2[10]);
      sst16<7,6,5,4>(st, base, a); }
    __syncthreads();
    { float2 a[16]; int base = expand4<1,2,3,4>(tid);      // wires (11,12,13,14)
      sld16<4,3,2,1>(st, base, a);
      apU16<2>(a, g_U2[b][12]); apU16<1>(a, g_U2[b][13]); apU16<0>(a, g_U2[b][14]);
      crx16<3,2>(a, g_crx2[11]); crx16<2,1>(a, g_crx2[12]); crx16<1,0>(a, g_crx2[13]);
      sst16<4,3,2,1>(st, base, a); }
    __syncthreads();
    // g4: wires (0,13,14,15) = l bits (11,2,1,0): U15; CRX(14,15); CRX(15,0); measure
    {
        float2 a[16]; int base = expand4<0,1,2,11>(tid);   // tid[7:0] -> l[10:3]
        sld16<11,2,1,0>(st, base, a);
        apU16<0>(a, g_U2[b][15]);
        crx16<1,0>(a, g_crx2[14]);                         // CRX(14,15)
        crx16<0,3>(a, g_crx2[15]);                         // CRX(15,0): ctrl bit0, tgt bit3
        float p[16];
#pragma unroll
        for (int i = 0; i < 16; i++) p[i] = a[i].x*a[i].x + a[i].y*a[i].y;
        float T = 0.f, S0 = 0.f, S13 = 0.f, S14 = 0.f, S15 = 0.f;
#pragma unroll
        for (int i = 0; i < 16; i++) {
            T += p[i];
            if (!((i >> 3) & 1)) S0  += p[i];
            if (!((i >> 2) & 1)) S13 += p[i];
            if (!((i >> 1) & 1)) S14 += p[i];
            if (!(i & 1))        S15 += p[i];
        }
        float z[16];
        z[0]  = 2.f*S0  - T;
        z[13] = 2.f*S13 - T;
        z[14] = 2.f*S14 - T;
        z[15] = 2.f*S15 - T;
#pragma unroll
        for (int w = 1; w <= 4; w++)  z[w] = ((slab >> (4 - w)) & 1) ? -T : T;
#pragma unroll
        for (int w = 5; w <= 12; w++) z[w] = ((base >> (15 - w)) & 1) ? -T : T;
#pragma unroll
        for (int w = 0; w < 16; w++) {
#pragma unroll
            for (int o = 16; o > 0; o >>= 1) z[w] += __shfl_xor_sync(0xFFFFFFFFu, z[w], o);
        }
        if ((tid & 31) == 0)
#pragma unroll
            for (int w = 0; w < 16; w++) atomicAdd(&red[w], z[w]);
    }
    __syncthreads();
    if (tid < 16) atomicAdd(&g_feats[b][tid], red[tid]);
}

// ---------------- FC + log_softmax ----------------
__global__ void k_fc(const float* __restrict__ fc_w, const float* __restrict__ fc_b,
                     float* __restrict__ out) {
    int b = threadIdx.x;
    if (b >= BATCH) return;
    float f[16];
#pragma unroll
    for (int w = 0; w < 16; w++) f[w] = g_feats[b][w];
    float l[NCLS], m = -1e30f;
    for (int c = 0; c < NCLS; c++) {
        float s = fc_b[c];
#pragma unroll
        for (int w = 0; w < 16; w++) s += f[w] * fc_w[c * 16 + w];
        l[c] = s; m = fmaxf(m, s);
    }
    float se = 0.f;
    for (int c = 0; c < NCLS; c++) se += expf(l[c] - m);
    float lse = m + logf(se);
    for (int c = 0; c < NCLS; c++) out[b * NCLS + c] = l[c] - lse;
}

extern "C" void kernel_launch(void* const* d_in, const int* in_sizes, int n_in,
                              void* d_out, int out_size) {
    const float* x    = (const float*)d_in[0];
    const float* w0   = (const float*)d_in[1];
    const float* x0   = (const float*)d_in[2];
    const float* w1   = (const float*)d_in[3];
    const float* x1   = (const float*)d_in[4];
    const float* fc_w = (const float*)d_in[5];
    const float* fc_b = (const float*)d_in[6];
    float* out = (float*)d_out;

    k_prep<<<1, 64>>>(x, w0, x0, w1, x1);
    dim3 grid(16, BATCH);
    k_pass1<<<grid, 256>>>();
    k_passB<<<grid, 256>>>();
    k_passC<<<grid, 256>>>();
    k_fc<<<1, 64>>>(fc_w, fc_b, out);
}

// round 6
// speedup vs baseline: 1.7915x; 1.2044x over previous
#include <cuda_runtime.h>
#include <math.h>

#define NQ    16
#define DIMN  65536
#define BATCH 64
#define NCLS  23

// ---------------- device scratch ----------------
__device__ float2 g_state[BATCH][DIMN];   // 32 MB
__device__ float2 g_v1[BATCH][NQ][2];     // layer-1 fused (Rot*RX)|0> columns
__device__ float2 g_U2[BATCH][NQ][4];     // layer-2 fused Rot*RX matrices
__device__ float2 g_U2p[BATCH][NQ][4];    // CRX-fused variants: q=0: U0*RX(crx1[15]); q>=1: RX(crx2[q-1])*Uq
__device__ float2 g_prefix[BATCH][16];    // entangled prefix over wires 0..3
__device__ float2 g_crx1[NQ];             // (cos th/2, sin th/2)
__device__ float2 g_crx2[NQ];
__device__ float  g_feats[BATCH][NQ];

// ---------------- helpers ----------------
__device__ __forceinline__ float2 cmul(float2 a, float2 b) {
    return make_float2(a.x*b.x - a.y*b.y, a.x*b.y + a.y*b.x);
}
// RX mix: t0' = c t0 - i s t1 ; t1' = c t1 - i s t0,  k=(c,s)
__device__ __forceinline__ void crxmix(float2& t0, float2& t1, float2 k) {
    float c = k.x, s = k.y;
    float2 n0 = make_float2(c*t0.x + s*t1.y, c*t0.y - s*t1.x);
    float2 n1 = make_float2(c*t1.x + s*t0.y, c*t1.y - s*t0.x);
    t0 = n0; t1 = n1;
}
__device__ __forceinline__ void apU(float2& a0, float2& a1,
                                    float2 u00, float2 u01, float2 u10, float2 u11) {
    float2 n0 = make_float2(u00.x*a0.x - u00.y*a0.y + u01.x*a1.x - u01.y*a1.y,
                            u00.x*a0.y + u00.y*a0.x + u01.x*a1.y + u01.y*a1.x);
    float2 n1 = make_float2(u10.x*a0.x - u10.y*a0.y + u11.x*a1.x - u11.y*a1.y,
                            u10.x*a0.y + u10.y*a0.x + u11.x*a1.y + u11.y*a1.x);
    a0 = n0; a1 = n1;
}
// 16-amp register tile, amp index i = (b3<<3)|(b2<<2)|(b1<<1)|b0
template<int B>
__device__ __forceinline__ void apU16(float2* a, const float2* U) {
    float2 u0 = U[0], u1 = U[1], u2 = U[2], u3 = U[3];
#pragma unroll
    for (int i = 0; i < 16; i++)
        if (!((i >> B) & 1)) apU(a[i], a[i | (1 << B)], u0, u1, u2, u3);
}
// conditional: pairs with ctrl-bit CB==1 use Up, else U (compile-time select)
template<int B, int CB>
__device__ __forceinline__ void apU16c(float2* a, const float2* U, const float2* Up) {
    float2 u0 = U[0],  u1 = U[1],  u2 = U[2],  u3 = U[3];
#pragma unroll
    for (int i = 0; i < 16; i++)
        if (!((i >> B) & 1) && !((i >> CB) & 1)) apU(a[i], a[i | (1 << B)], u0, u1, u2, u3);
    float2 p0 = Up[0], p1 = Up[1], p2 = Up[2], p3 = Up[3];
#pragma unroll
    for (int i = 0; i < 16; i++)
        if (!((i >> B) & 1) && ((i >> CB) & 1)) apU(a[i], a[i | (1 << B)], p0, p1, p2, p3);
}
template<int CB, int TB>
__device__ __forceinline__ void crx16(float2* a, float2 k) {
#pragma unroll
    for (int i = 0; i < 16; i++)
        if (((i >> CB) & 1) && !((i >> TB) & 1)) crxmix(a[i], a[i | (1 << TB)], k);
}
#define SWZ(e) ((e) ^ (((e) >> 4) & 0xF))

template<int P0, int P1, int P2, int P3>   // ascending insert positions
__device__ __forceinline__ int expand4(int t) {
    t = ((t >> P0) << (P0 + 1)) | (t & ((1 << P0) - 1));
    t = ((t >> P1) << (P1 + 1)) | (t & ((1 << P1) - 1));
    t = ((t >> P2) << (P2 + 1)) | (t & ((1 << P2) - 1));
    t = ((t >> P3) << (P3 + 1)) | (t & ((1 << P3) - 1));
    return t;
}
// bit3->PA, bit2->PB, bit1->PC, bit0->PD
template<int PA, int PB, int PC, int PD>
__device__ __forceinline__ void sld16(const float2* st, int base, float2* a) {
#pragma unroll
    for (int i = 0; i < 16; i++) {
        int idx = base | (((i>>3)&1)<<PA) | (((i>>2)&1)<<PB) | (((i>>1)&1)<<PC) | ((i&1)<<PD);
        a[i] = st[SWZ(idx)];
    }
}
template<int PA, int PB, int PC, int PD>
__device__ __forceinline__ void sst16(float2* st, int base, const float2* a) {
#pragma unroll
    for (int i = 0; i < 16; i++) {
        int idx = base | (((i>>3)&1)<<PA) | (((i>>2)&1)<<PB) | (((i>>1)&1)<<PC) | ((i&1)<<PD);
        st[SWZ(idx)] = a[i];
    }
}

// fused U = Rot(phi,theta,omega) * RX(xv); out[4] = {U00,U01,U10,U11}
__device__ __forceinline__ void fuse_rot_rx(float phi, float th, float om, float xv, float2* out) {
    float sx, cx; sincosf(0.5f * xv, &sx, &cx);
    float st, ct; sincosf(0.5f * th, &st, &ct);
    float sa, ca; sincosf(0.5f * (phi + om), &sa, &ca);
    float sb, cb; sincosf(0.5f * (phi - om), &sb, &cb);
    float2 A = make_float2( ca*ct, -sa*ct);
    float2 B = make_float2(-cb*st, -sb*st);
    float2 C = make_float2( cb*st, -sb*st);
    float2 D = make_float2( ca*ct,  sa*ct);
    out[0] = make_float2(A.x*cx + B.y*sx,  A.y*cx - B.x*sx);
    out[1] = make_float2(A.y*sx + B.x*cx, -A.x*sx + B.y*cx);
    out[2] = make_float2(C.x*cx + D.y*sx,  C.y*cx - D.x*sx);
    out[3] = make_float2(C.y*sx + D.x*cx, -C.x*sx + D.y*cx);
}
// (-i s)*z
__device__ __forceinline__ float2 mih(float s, float2 z) { return make_float2(s*z.y, -s*z.x); }
__device__ __forceinline__ float2 caxpy(float c, float2 a, float2 b) {  // c*a + b
    return make_float2(c*a.x + b.x, c*a.y + b.y);
}
// Up = RX(k) * U
__device__ __forceinline__ void rx_left(float2 k, const float2* U, float2* Up) {
    float c = k.x, s = k.y;
    Up[0] = caxpy(c, U[0], mih(s, U[2]));
    Up[1] = caxpy(c, U[1], mih(s, U[3]));
    Up[2] = caxpy(c, U[2], mih(s, U[0]));
    Up[3] = caxpy(c, U[3], mih(s, U[1]));
}
// Up = U * RX(k)
__device__ __forceinline__ void rx_right(float2 k, const float2* U, float2* Up) {
    float c = k.x, s = k.y;
    Up[0] = caxpy(c, U[0], mih(s, U[1]));
    Up[1] = caxpy(c, U[1], mih(s, U[0]));
    Up[2] = caxpy(c, U[2], mih(s, U[3]));
    Up[3] = caxpy(c, U[3], mih(s, U[2]));
}

// ---------------- prep: 64 blocks (samples) x 16 threads (wires) ----------------
__global__ void k_prep(const float* __restrict__ x,  const float* __restrict__ w0,
                       const float* __restrict__ x0, const float* __restrict__ w1,
                       const float* __restrict__ x1) {
    int b = blockIdx.x, q = threadIdx.x;
    __shared__ float2 vsh[4][2];
    float xv = x[b * NQ + q];
    float2 U[4];
    fuse_rot_rx(w0[q*3+0], w0[q*3+1], w0[q*3+2], xv, U);   // layer 1
    g_v1[b][q][0] = U[0]; g_v1[b][q][1] = U[2];            // column 0
    if (q < 4) { vsh[q][0] = U[0]; vsh[q][1] = U[2]; }
    fuse_rot_rx(w1[q*3+0], w1[q*3+1], w1[q*3+2], xv, U);   // layer 2
    g_U2[b][q][0] = U[0]; g_U2[b][q][1] = U[1];
    g_U2[b][q][2] = U[2]; g_U2[b][q][3] = U[3];
    if (b == 0) {
        float s, c;
        sincosf(0.5f * x0[q], &s, &c); g_crx1[q] = make_float2(c, s);
        sincosf(0.5f * x1[q], &s, &c); g_crx2[q] = make_float2(c, s);
    }
    // CRX-fused matrices
    {
        float s, c; float2 Up[4];
        if (q == 0) {
            sincosf(0.5f * x0[15], &s, &c);            // crx1[15], U0 after it
            rx_right(make_float2(c, s), U, Up);
        } else {
            sincosf(0.5f * x1[q-1], &s, &c);           // crx2[q-1] after Uq
            rx_left(make_float2(c, s), U, Up);
        }
        g_U2p[b][q][0] = Up[0]; g_U2p[b][q][1] = Up[1];
        g_U2p[b][q][2] = Up[2]; g_U2p[b][q][3] = Up[3];
    }
    g_feats[b][q] = 0.f;
    __syncthreads();
    if (q == 0) {
        // prefix over wires 0..3 (j = b0 b1 b2 b3), CRX(0,1),(1,2),(2,3)
        float2 amp[16];
#pragma unroll
        for (int j = 0; j < 16; j++) {
            int b0=(j>>3)&1, b1=(j>>2)&1, b2=(j>>1)&1, b3=j&1;
            amp[j] = cmul(cmul(vsh[0][b0], vsh[1][b1]), cmul(vsh[2][b2], vsh[3][b3]));
        }
        float s, c;
        sincosf(0.5f * x0[0], &s, &c); { float2 k = make_float2(c, s);
            crxmix(amp[8],amp[12],k);  crxmix(amp[9],amp[13],k);
            crxmix(amp[10],amp[14],k); crxmix(amp[11],amp[15],k); }
        sincosf(0.5f * x0[1], &s, &c); { float2 k = make_float2(c, s);
            crxmix(amp[4],amp[6],k);   crxmix(amp[5],amp[7],k);
            crxmix(amp[12],amp[14],k); crxmix(amp[13],amp[15],k); }
        sincosf(0.5f * x0[2], &s, &c); { float2 k = make_float2(c, s);
            crxmix(amp[2],amp[3],k);   crxmix(amp[6],amp[7],k);
            crxmix(amp[10],amp[11],k); crxmix(amp[14],amp[15],k); }
#pragma unroll
        for (int j = 0; j < 16; j++) g_prefix[b][j] = amp[j];
    }
}

// ---------------- pass1: build state + L1 CRX(3,4)..(14,15) -----------------
// slab = wires 0..3 (global bits 15..12); local l bits 11..0 = wires 4..15
__global__ void __launch_bounds__(256) k_pass1() {
    __shared__ float2 st[4096];
    int slab = blockIdx.x, b = blockIdx.y, tid = threadIdx.x;
    // g1: wires (4,5,6,7) = l bits (11,10,9,8): construct; fold CRX(3,4); CRX(4,5),(5,6),(6,7)
    {
        int base = expand4<8,9,10,11>(tid);           // tid[7:0] -> l[7:0]
        float2 common = g_prefix[b][slab];
#pragma unroll
        for (int q = 8; q < 16; q++) common = cmul(common, g_v1[b][q][(base >> (15 - q)) & 1]);
        float2 v40 = g_v1[b][4][0], v41 = g_v1[b][4][1];
        if (slab & 1) crxmix(v40, v41, g_crx1[3]);    // ctrl wire3 = slab bit0
        float2 v50 = g_v1[b][5][0], v51 = g_v1[b][5][1];
        float2 v60 = g_v1[b][6][0], v61 = g_v1[b][6][1];
        float2 v70 = g_v1[b][7][0], v71 = g_v1[b][7][1];
        float2 t45[4], t67[4];
        t45[0]=cmul(v40,v50); t45[1]=cmul(v40,v51); t45[2]=cmul(v41,v50); t45[3]=cmul(v41,v51);
        t67[0]=cmul(v60,v70); t67[1]=cmul(v60,v71); t67[2]=cmul(v61,v70); t67[3]=cmul(v61,v71);
        float2 a[16];
#pragma unroll
        for (int i = 0; i < 16; i++) a[i] = cmul(cmul(t45[i >> 2], t67[i & 3]), common);
        crx16<3,2>(a, g_crx1[4]);
        crx16<2,1>(a, g_crx1[5]);
        crx16<1,0>(a, g_crx1[6]);
        sst16<11,10,9,8>(st, base, a);
    }
    __syncthreads();
    { float2 a[16]; int base = expand4<5,6,7,8>(tid);   // wires (7,8,9,10)
      sld16<8,7,6,5>(st, base, a);
      crx16<3,2>(a, g_crx1[7]); crx16<2,1>(a, g_crx1[8]); crx16<1,0>(a, g_crx1[9]);
      sst16<8,7,6,5>(st, base, a); }
    __syncthreads();
    { float2 a[16]; int base = expand4<2,3,4,5>(tid);   // wires (10,11,12,13)
      sld16<5,4,3,2>(st, base, a);
      crx16<3,2>(a, g_crx1[10]); crx16<2,1>(a, g_crx1[11]); crx16<1,0>(a, g_crx1[12]);
      sst16<5,4,3,2>(st, base, a); }
    __syncthreads();
    {   // wires (12,13,14,15) = bits (3,2,1,0): CRX(13,14),(14,15); write out
        float2 a[16]; int base = tid << 4;
        sld16<3,2,1,0>(st, base, a);
        crx16<2,1>(a, g_crx1[13]); crx16<1,0>(a, g_crx1[14]);
        float4* out = (float4*)&g_state[b][(slab << 12) | base];
#pragma unroll
        for (int j = 0; j < 8; j++)
            out[j] = make_float4(a[2*j].x, a[2*j].y, a[2*j+1].x, a[2*j+1].y);
    }
}

// ---------------- passB: slab = wires 6..9 (global bits 9..6) ----------------
// l bits 11..6 = wires 0..5 (global 15..10); l bits 5..0 = wires 10..15 (global 5..0)
__device__ __forceinline__ int mapB(int l, int s) {
    return ((l >> 6) << 10) | (s << 6) | (l & 0x3F);
}
__global__ void __launch_bounds__(256, 3) k_passB() {
    __shared__ float2 st[4096];
    int slab = blockIdx.x, b = blockIdx.y, tid = threadIdx.x;
    // g1: wires (15,0,1,2) = l bits (0,11,10,9):
    // [CRX(15,0)L1 + U0] ; [U1 + CRX(0,1)] ; [U2 + CRX(1,2)]  (all CRX-fused)
    {
        float2 a[16];
        int base = expand4<0,9,10,11>(tid);           // tid[7:0] -> l[8:1]
#pragma unroll
        for (int j = 0; j < 8; j++) {                 // pair (j, j|8) adjacent (l bit0)
            int lo = base | (((j>>2)&1)<<11) | (((j>>1)&1)<<10) | ((j&1)<<9);
            float4 v = *(const float4*)&g_state[b][mapB(lo, slab)];
            a[j]     = make_float2(v.x, v.y);
            a[j | 8] = make_float2(v.z, v.w);
        }
        apU16c<2,3>(a, g_U2[b][0], g_U2p[b][0]);   // ctrl bit3 = wire15
        apU16c<1,2>(a, g_U2[b][1], g_U2p[b][1]);   // ctrl bit2 = wire0
        apU16c<0,1>(a, g_U2[b][2], g_U2p[b][2]);   // ctrl bit1 = wire1
        sst16<0,11,10,9>(st, base, a);
    }
    __syncthreads();
    // g2: wires (2,3,4,5) = l bits (9,8,7,6): [U3+CRX(2,3)];[U4+CRX(3,4)];[U5+CRX(4,5)]; store
    {
        float2 a[16]; int base = expand4<6,7,8,9>(tid);
        sld16<9,8,7,6>(st, base, a);
        apU16c<2,3>(a, g_U2[b][3], g_U2p[b][3]);
        apU16c<1,2>(a, g_U2[b][4], g_U2p[b][4]);
        apU16c<0,1>(a, g_U2[b][5], g_U2p[b][5]);
#pragma unroll
        for (int i = 0; i < 16; i++) {
            int l = base | (((i>>3)&1)<<9) | (((i>>2)&1)<<8) | (((i>>1)&1)<<7) | ((i&1)<<6);
            g_state[b][mapB(l, slab)] = a[i];
        }
    }
}

// ---------------- passC: slab = wires 1..4 (global bits 14..11) --------------
// l bit 11 = wire 0 (global bit 15); l bits 10..0 = wires 5..15 (global 10..0)
// gates U6..U15 (CRX-fused), CRX(15,0) L2, fused measurement. READ-ONLY.
__device__ __forceinline__ int mapC(int l, int s) {
    return ((l >> 11) << 15) | (s << 11) | (l & 0x7FF);
}
__global__ void __launch_bounds__(256, 3) k_passC() {
    __shared__ float2 st[4096];
    __shared__ float red[16];
    int slab = blockIdx.x, b = blockIdx.y, tid = threadIdx.x;
    if (tid < 16) red[tid] = 0.f;
    // g1: wires (5,6,7,8) = l bits (10,9,8,7): [U6+CRX(5,6)];[U7+CRX(6,7)];[U8+CRX(7,8)]
    {
        float2 a[16]; int base = expand4<7,8,9,10>(tid);   // tid[6:0]->l[6:0], tid7->l11
#pragma unroll
        for (int i = 0; i < 16; i++) {
            int l = base | (((i>>3)&1)<<10) | (((i>>2)&1)<<9) | (((i>>1)&1)<<8) | ((i&1)<<7);
            a[i] = g_state[b][mapC(l, slab)];
        }
        apU16c<2,3>(a, g_U2[b][6], g_U2p[b][6]);
        apU16c<1,2>(a, g_U2[b][7], g_U2p[b][7]);
        apU16c<0,1>(a, g_U2[b][8], g_U2p[b][8]);
        sst16<10,9,8,7>(st, base, a);
    }
    __syncthreads();
    { float2 a[16]; int base = expand4<4,5,6,7>(tid);      // wires (8,9,10,11)
      sld16<7,6,5,4>(st, base, a);
      apU16c<2,3>(a, g_U2[b][9],  g_U2p[b][9]);
      apU16c<1,2>(a, g_U2[b][10], g_U2p[b][10]);
      apU16c<0,1>(a, g_U2[b][11], g_U2p[b][11]);
      sst16<7,6,5,4>(st, base, a); }
    __syncthreads();
    { float2 a[16]; int base = expand4<1,2,3,4>(tid);      // wires (11,12,13,14)
      sld16<4,3,2,1>(st, base, a);
      apU16c<2,3>(a, g_U2[b][12], g_U2p[b][12]);
      apU16c<1,2>(a, g_U2[b][13], g_U2p[b][13]);
      apU16c<0,1>(a, g_U2[b][14], g_U2p[b][14]);
      sst16<4,3,2,1>(st, base, a); }
    __syncthreads();
    // g4: wires (0,13,14,15) = l bits (11,2,1,0): [U15+CRX(14,15)]; CRX(15,0); measure
    {
        float2 a[16]; int base = expand4<0,1,2,11>(tid);   // tid[7:0] -> l[10:3]
        sld16<11,2,1,0>(st, base, a);
        apU16c<0,1>(a, g_U2[b][15], g_U2p[b][15]);         // ctrl bit1 = wire14
        crx16<0,3>(a, g_crx2[15]);                         // CRX(15,0): ctrl bit0, tgt bit3
        float p[16];
#pragma unroll
        for (int i = 0; i < 16; i++) p[i] = a[i].x*a[i].x + a[i].y*a[i].y;
        float T = 0.f, S0 = 0.f, S13 = 0.f, S14 = 0.f, S15 = 0.f;
#pragma unroll
        for (int i = 0; i < 16; i++) {
            T += p[i];
            if (!((i >> 3) & 1)) S0  += p[i];
            if (!((i >> 2) & 1)) S13 += p[i];
            if (!((i >> 1) & 1)) S14 += p[i];
            if (!(i & 1))        S15 += p[i];
        }
        float z[16];
        z[0]  = 2.f*S0  - T;
        z[13] = 2.f*S13 - T;
        z[14] = 2.f*S14 - T;
        z[15] = 2.f*S15 - T;
#pragma unroll
        for (int w = 1; w <= 4; w++)  z[w] = ((slab >> (4 - w)) & 1) ? -T : T;
#pragma unroll
        for (int w = 5; w <= 12; w++) z[w] = ((base >> (15 - w)) & 1) ? -T : T;
#pragma unroll
        for (int w = 0; w < 16; w++) {
#pragma unroll
            for (int o = 16; o > 0; o >>= 1) z[w] += __shfl_xor_sync(0xFFFFFFFFu, z[w], o);
        }
        if ((tid & 31) == 0)
#pragma unroll
            for (int w = 0; w < 16; w++) atomicAdd(&red[w], z[w]);
    }
    __syncthreads();
    if (tid < 16) atomicAdd(&g_feats[b][tid], red[tid]);
}

// ---------------- FC + log_softmax ----------------
__global__ void k_fc(const float* __restrict__ fc_w, const float* __restrict__ fc_b,
                     float* __restrict__ out) {
    int b = threadIdx.x;
    if (b >= BATCH) return;
    float f[16];
#pragma unroll
    for (int w = 0; w < 16; w++) f[w] = g_feats[b][w];
    float l[NCLS], m = -1e30f;
    for (int c = 0; c < NCLS; c++) {
        float s = fc_b[c];
#pragma unroll
        for (int w = 0; w < 16; w++) s += f[w] * fc_w[c * 16 + w];
        l[c] = s; m = fmaxf(m, s);
    }
    float se = 0.f;
    for (int c = 0; c < NCLS; c++) se += expf(l[c] - m);
    float lse = m + logf(se);
    for (int c = 0; c < NCLS; c++) out[b * NCLS + c] = l[c] - lse;
}

extern "C" void kernel_launch(void* const* d_in, const int* in_sizes, int n_in,
                              void* d_out, int out_size) {
    const float* x    = (const float*)d_in[0];
    const float* w0   = (const float*)d_in[1];
    const float* x0   = (const float*)d_in[2];
    const float* w1   = (const float*)d_in[3];
    const float* x1   = (const float*)d_in[4];
    const float* fc_w = (const float*)d_in[5];
    const float* fc_b = (const float*)d_in[6];
    float* out = (float*)d_out;

    k_prep<<<64, 16>>>(x, w0, x0, w1, x1);
    dim3 grid(16, BATCH);
    k_pass1<<<grid, 256>>>();
    k_passB<<<grid, 256>>>();
    k_passC<<<grid, 256>>>();
    k_fc<<<1, 64>>>(fc_w, fc_b, out);
}

// round 8
// speedup vs baseline: 1.8063x; 1.0083x over previous
#include <cuda_runtime.h>
#include <math.h>

#define NQ    16
#define DIMN  65536
#define BATCH 64
#define NCLS  23

// ---------------- device scratch ----------------
__device__ float2 g_state[BATCH][DIMN];   // 32 MB
__device__ float2 g_v1[BATCH][NQ][2];     // layer-1 fused (Rot*RX)|0> columns
__device__ float2 g_U2[BATCH][NQ][4];     // layer-2 fused Rot*RX matrices
__device__ float2 g_U2p[BATCH][NQ][4];    // CRX-fused: q=0: U0*RX(crx1[15]); q>=1: RX(crx2[q-1])*Uq
__device__ float2 g_prefix[BATCH][16];    // entangled prefix over wires 0..3
__device__ float2 g_crx1[NQ];             // (cos th/2, sin th/2)
__device__ float2 g_crx2[NQ];
__device__ float  g_feats[BATCH][NQ];

// ---------------- helpers ----------------
__device__ __forceinline__ float2 cmul(float2 a, float2 b) {
    return make_float2(a.x*b.x - a.y*b.y, a.x*b.y + a.y*b.x);
}
__device__ __forceinline__ void crxmix(float2& t0, float2& t1, float2 k) {
    float c = k.x, s = k.y;
    float2 n0 = make_float2(c*t0.x + s*t1.y, c*t0.y - s*t1.x);
    float2 n1 = make_float2(c*t1.x + s*t0.y, c*t1.y - s*t0.x);
    t0 = n0; t1 = n1;
}
__device__ __forceinline__ void apU(float2& a0, float2& a1,
                                    float2 u00, float2 u01, float2 u10, float2 u11) {
    float2 n0 = make_float2(u00.x*a0.x - u00.y*a0.y + u01.x*a1.x - u01.y*a1.y,
                            u00.x*a0.y + u00.y*a0.x + u01.x*a1.y + u01.y*a1.x);
    float2 n1 = make_float2(u10.x*a0.x - u10.y*a0.y + u11.x*a1.x - u11.y*a1.y,
                            u10.x*a0.y + u10.y*a0.x + u11.x*a1.y + u11.y*a1.x);
    a0 = n0; a1 = n1;
}
// 32-amp register tile, amp index i = (b4<<4)|(b3<<3)|(b2<<2)|(b1<<1)|b0
template<int B, int CB>
__device__ __forceinline__ void apU32c(float2* a, const float2* U, const float2* Up) {
    float2 u0 = U[0],  u1 = U[1],  u2 = U[2],  u3 = U[3];
#pragma unroll
    for (int i = 0; i < 32; i++)
        if (!((i >> B) & 1) && !((i >> CB) & 1)) apU(a[i], a[i | (1 << B)], u0, u1, u2, u3);
    float2 p0 = Up[0], p1 = Up[1], p2 = Up[2], p3 = Up[3];
#pragma unroll
    for (int i = 0; i < 32; i++)
        if (!((i >> B) & 1) && ((i >> CB) & 1)) apU(a[i], a[i | (1 << B)], p0, p1, p2, p3);
}
template<int CB, int TB>
__device__ __forceinline__ void crx32(float2* a, float2 k) {
#pragma unroll
    for (int i = 0; i < 32; i++)
        if (((i >> CB) & 1) && !((i >> TB) & 1)) crxmix(a[i], a[i | (1 << TB)], k);
}
// swizzle: bank bits = l[3:0] ^ l[7:4] ^ (l8 ? 0xC : 0) ^ (l9 ? 0x1 : 0)
// rank-4 over every warp access pattern below -> 2-way (float2 minimum) conflicts.
__device__ __forceinline__ int SWZ(int e) {
    int h = (e >> 4) & 0xF;
    h ^= (e >> 8 & 1) * 0xC;
    h ^= (e >> 9 & 1);
    return e ^ h;
}

template<int P0, int P1, int P2, int P3, int P4>   // ascending insert positions
__device__ __forceinline__ int expand5(int t) {
    t = ((t >> P0) << (P0 + 1)) | (t & ((1 << P0) - 1));
    t = ((t >> P1) << (P1 + 1)) | (t & ((1 << P1) - 1));
    t = ((t >> P2) << (P2 + 1)) | (t & ((1 << P2) - 1));
    t = ((t >> P3) << (P3 + 1)) | (t & ((1 << P3) - 1));
    t = ((t >> P4) << (P4 + 1)) | (t & ((1 << P4) - 1));
    return t;
}
// bit4->PA, bit3->PB, bit2->PC, bit1->PD, bit0->PE
template<int PA, int PB, int PC, int PD, int PE>
__device__ __forceinline__ void sld32(const float2* st, int base, float2* a) {
#pragma unroll
    for (int i = 0; i < 32; i++) {
        int idx = base | (((i>>4)&1)<<PA) | (((i>>3)&1)<<PB) | (((i>>2)&1)<<PC)
                       | (((i>>1)&1)<<PD) | ((i&1)<<PE);
        a[i] = st[SWZ(idx)];
    }
}
template<int PA, int PB, int PC, int PD, int PE>
__device__ __forceinline__ void sst32(float2* st, int base, const float2* a) {
#pragma unroll
    for (int i = 0; i < 32; i++) {
        int idx = base | (((i>>4)&1)<<PA) | (((i>>3)&1)<<PB) | (((i>>2)&1)<<PC)
                       | (((i>>1)&1)<<PD) | ((i&1)<<PE);
        st[SWZ(idx)] = a[i];
    }
}

// fused U = Rot(phi,theta,omega) * RX(xv); out[4] = {U00,U01,U10,U11}
__device__ __forceinline__ void fuse_rot_rx(float phi, float th, float om, float xv, float2* out) {
    float sx, cx; sincosf(0.5f * xv, &sx, &cx);
    float st, ct; sincosf(0.5f * th, &st, &ct);
    float sa, ca; sincosf(0.5f * (phi + om), &sa, &ca);
    float sb, cb; sincosf(0.5f * (phi - om), &sb, &cb);
    float2 A = make_float2( ca*ct, -sa*ct);
    float2 B = make_float2(-cb*st, -sb*st);
    float2 C = make_float2( cb*st, -sb*st);
    float2 D = make_float2( ca*ct,  sa*ct);
    out[0] = make_float2(A.x*cx + B.y*sx,  A.y*cx - B.x*sx);
    out[1] = make_float2(A.y*sx + B.x*cx, -A.x*sx + B.y*cx);
    out[2] = make_float2(C.x*cx + D.y*sx,  C.y*cx - D.x*sx);
    out[3] = make_float2(C.y*sx + D.x*cx, -C.x*sx + D.y*cx);
}
__device__ __forceinline__ float2 mih(float s, float2 z) { return make_float2(s*z.y, -s*z.x); }
__device__ __forceinline__ float2 caxpy(float c, float2 a, float2 b) {
    return make_float2(c*a.x + b.x, c*a.y + b.y);
}
// Up = RX(k) * U
__device__ __forceinline__ void rx_left(float2 k, const float2* U, float2* Up) {
    float c = k.x, s = k.y;
    Up[0] = caxpy(c, U[0], mih(s, U[2]));
    Up[1] = caxpy(c, U[1], mih(s, U[3]));
    Up[2] = caxpy(c, U[2], mih(s, U[0]));
    Up[3] = caxpy(c, U[3], mih(s, U[1]));
}
// Up = U * RX(k)
__device__ __forceinline__ void rx_right(float2 k, const float2* U, float2* Up) {
    float c = k.x, s = k.y;
    Up[0] = caxpy(c, U[0], mih(s, U[1]));
    Up[1] = caxpy(c, U[1], mih(s, U[0]));
    Up[2] = caxpy(c, U[2], mih(s, U[3]));
    Up[3] = caxpy(c, U[3], mih(s, U[2]));
}

// ---------------- prep: 64 blocks (samples) x 16 threads (wires) ----------------
__global__ void k_prep(const float* __restrict__ x,  const float* __restrict__ w0,
                       const float* __restrict__ x0, const float* __restrict__ w1,
                       const float* __restrict__ x1) {
    int b = blockIdx.x, q = threadIdx.x;
    __shared__ float2 vsh[4][2];
    float xv = x[b * NQ + q];
    float2 U[4];
    fuse_rot_rx(w0[q*3+0], w0[q*3+1], w0[q*3+2], xv, U);   // layer 1
    g_v1[b][q][0] = U[0]; g_v1[b][q][1] = U[2];            // column 0
    if (q < 4) { vsh[q][0] = U[0]; vsh[q][1] = U[2]; }
    fuse_rot_rx(w1[q*3+0], w1[q*3+1], w1[q*3+2], xv, U);   // layer 2
    g_U2[b][q][0] = U[0]; g_U2[b][q][1] = U[1];
    g_U2[b][q][2] = U[2]; g_U2[b][q][3] = U[3];
    if (b == 0) {
        float s, c;
        sincosf(0.5f * x0[q], &s, &c); g_crx1[q] = make_float2(c, s);
        sincosf(0.5f * x1[q], &s, &c); g_crx2[q] = make_float2(c, s);
    }
    {
        float s, c; float2 Up[4];
        if (q == 0) {
            sincosf(0.5f * x0[15], &s, &c);            // crx1[15] precedes U0
            rx_right(make_float2(c, s), U, Up);
        } else {
            sincosf(0.5f * x1[q-1], &s, &c);           // crx2[q-1] follows Uq
            rx_left(make_float2(c, s), U, Up);
        }
        g_U2p[b][q][0] = Up[0]; g_U2p[b][q][1] = Up[1];
        g_U2p[b][q][2] = Up[2]; g_U2p[b][q][3] = Up[3];
    }
    g_feats[b][q] = 0.f;
    __syncthreads();
    if (q == 0) {
        // prefix over wires 0..3 (j = b0 b1 b2 b3), CRX(0,1),(1,2),(2,3)
        float2 amp[16];
#pragma unroll
        for (int j = 0; j < 16; j++) {
            int b0=(j>>3)&1, b1=(j>>2)&1, b2=(j>>1)&1, b3=j&1;
            amp[j] = cmul(cmul(vsh[0][b0], vsh[1][b1]), cmul(vsh[2][b2], vsh[3][b3]));
        }
        float s, c;
        sincosf(0.5f * x0[0], &s, &c); { float2 k = make_float2(c, s);
            crxmix(amp[8],amp[12],k);  crxmix(amp[9],amp[13],k);
            crxmix(amp[10],amp[14],k); crxmix(amp[11],amp[15],k); }
        sincosf(0.5f * x0[1], &s, &c); { float2 k = make_float2(c, s);
            crxmix(amp[4],amp[6],k);   crxmix(amp[5],amp[7],k);
            crxmix(amp[12],amp[14],k); crxmix(amp[13],amp[15],k); }
        sincosf(0.5f * x0[2], &s, &c); { float2 k = make_float2(c, s);
            crxmix(amp[2],amp[3],k);   crxmix(amp[6],amp[7],k);
            crxmix(amp[10],amp[11],k); crxmix(amp[14],amp[15],k); }
#pragma unroll
        for (int j = 0; j < 16; j++) g_prefix[b][j] = amp[j];
    }
}

// ---------------- pass1: build state + L1 CRX(3,4)..(14,15) -----------------
// slab = wires 0..3 (global bits 15..12); local l bits 11..0 = wires 4..15
__global__ void __launch_bounds__(128, 3) k_pass1() {
    __shared__ float2 st[4096];
    int slab = blockIdx.x, b = blockIdx.y, tid = threadIdx.x;
    // g1: wires (4,5,6,7,8) = l bits (11,10,9,8,7): construct; fold CRX(3,4); CRX(4,5)..(7,8)
    {
        int base = expand5<7,8,9,10,11>(tid);         // tid[6:0] -> l[6:0]
        float2 common = g_prefix[b][slab];
#pragma unroll
        for (int q = 9; q < 16; q++) common = cmul(common, g_v1[b][q][(base >> (15 - q)) & 1]);
        float2 v40 = g_v1[b][4][0], v41 = g_v1[b][4][1];
        if (slab & 1) crxmix(v40, v41, g_crx1[3]);    // ctrl wire3 = slab bit0
        float2 v50 = g_v1[b][5][0], v51 = g_v1[b][5][1];
        float2 v60 = g_v1[b][6][0], v61 = g_v1[b][6][1];
        float2 v70 = g_v1[b][7][0], v71 = g_v1[b][7][1];
        float2 v80 = g_v1[b][8][0], v81 = g_v1[b][8][1];
        float2 t45[4], t678[8];
        t45[0]=cmul(v40,v50); t45[1]=cmul(v40,v51); t45[2]=cmul(v41,v50); t45[3]=cmul(v41,v51);
#pragma unroll
        for (int j = 0; j < 8; j++)
            t678[j] = cmul(cmul((j>>2)?v61:v60, ((j>>1)&1)?v71:v70), (j&1)?v81:v80);
        float2 a[32];
#pragma unroll
        for (int i = 0; i < 32; i++) a[i] = cmul(cmul(t45[i >> 3], t678[i & 7]), common);
        crx32<4,3>(a, g_crx1[4]); crx32<3,2>(a, g_crx1[5]);
        crx32<2,1>(a, g_crx1[6]); crx32<1,0>(a, g_crx1[7]);
        sst32<11,10,9,8,7>(st, base, a);
    }
    __syncthreads();
    // g2: wires (8,9,10,11,12) = l bits (7,6,5,4,3): CRX(8,9)..(11,12)
    {
        float2 a[32]; int base = expand5<3,4,5,6,7>(tid);
        sld32<7,6,5,4,3>(st, base, a);
        crx32<4,3>(a, g_crx1[8]);  crx32<3,2>(a, g_crx1[9]);
        crx32<2,1>(a, g_crx1[10]); crx32<1,0>(a, g_crx1[11]);
        sst32<7,6,5,4,3>(st, base, a);
    }
    __syncthreads();
    // g3: wires (11,12,13,14,15) = l bits (4,3,2,1,0): CRX(12,13),(13,14),(14,15); write out
    {
        float2 a[32]; int base = tid << 5;
        sld32<4,3,2,1,0>(st, base, a);
        crx32<3,2>(a, g_crx1[12]); crx32<2,1>(a, g_crx1[13]); crx32<1,0>(a, g_crx1[14]);
        float4* out = (float4*)&g_state[b][(slab << 12) | base];
#pragma unroll
        for (int j = 0; j < 16; j++)
            out[j] = make_float4(a[2*j].x, a[2*j].y, a[2*j+1].x, a[2*j+1].y);
    }
}

// ---------------- passB: slab = wires 6..9 (global bits 9..6) ----------------
// l bits 11..6 = wires 0..5 (global 15..10); l bits 5..0 = wires 10..15 (global 5..0)
__device__ __forceinline__ int mapB(int l, int s) {
    return ((l >> 6) << 10) | (s << 6) | (l & 0x3F);
}
__global__ void __launch_bounds__(128, 3) k_passB() {
    __shared__ float2 st[4096];
    int slab = blockIdx.x, b = blockIdx.y, tid = threadIdx.x;
    // g1: wires (15,0,1,2,3) = l bits (0,11,10,9,8):
    // [CRX(15,0)L1+U0]; [U1+CRX(0,1)]; [U2+CRX(1,2)]; [U3+CRX(2,3)]
    {
        float2 a[32];
        int base = expand5<0,8,9,10,11>(tid);         // tid[6:0] -> l[7:1]
#pragma unroll
        for (int j = 0; j < 16; j++) {                // pair (j, j|16) adjacent (l bit0)
            int lo = base | (((j>>3)&1)<<11) | (((j>>2)&1)<<10) | (((j>>1)&1)<<9) | ((j&1)<<8);
            float4 v = *(const float4*)&g_state[b][mapB(lo, slab)];
            a[j]      = make_float2(v.x, v.y);
            a[j | 16] = make_float2(v.z, v.w);
        }
        apU32c<3,4>(a, g_U2[b][0], g_U2p[b][0]);   // ctrl b4 = wire15
        apU32c<2,3>(a, g_U2[b][1], g_U2p[b][1]);   // ctrl b3 = wire0
        apU32c<1,2>(a, g_U2[b][2], g_U2p[b][2]);   // ctrl b2 = wire1
        apU32c<0,1>(a, g_U2[b][3], g_U2p[b][3]);   // ctrl b1 = wire2
        sst32<0,11,10,9,8>(st, base, a);
    }
    __syncthreads();
    // g2: wires (3,4,5,14,15) = l bits (8,7,6,1,0): [U4+CRX(3,4)]; [U5+CRX(4,5)]; store
    {
        float2 a[32]; int base = expand5<0,1,6,7,8>(tid);
        sld32<8,7,6,1,0>(st, base, a);
        apU32c<3,4>(a, g_U2[b][4], g_U2p[b][4]);
        apU32c<2,3>(a, g_U2[b][5], g_U2p[b][5]);
#pragma unroll
        for (int i = 0; i < 32; i += 2) {             // i,i+1 differ in b0 = l bit0
            int lo = base | (((i>>4)&1)<<8) | (((i>>3)&1)<<7) | (((i>>2)&1)<<6) | (((i>>1)&1)<<1);
            *(float4*)&g_state[b][mapB(lo, slab)] =
                make_float4(a[i].x, a[i].y, a[i+1].x, a[i+1].y);
        }
    }
}

// ---------------- passC: slab = wires 1..4 (global bits 14..11) --------------
// l bit 11 = wire 0 (global bit 15); l bits 10..0 = wires 5..15 (global 10..0)
// gates U6..U15 (CRX-fused), CRX(15,0) L2, fused measurement. READ-ONLY.
__device__ __forceinline__ int mapC(int l, int s) {
    return ((l >> 11) << 15) | (s << 11) | (l & 0x7FF);
}
__global__ void __launch_bounds__(128, 3) k_passC() {
    __shared__ float2 st[4096];
    __shared__ float red[16];
    int slab = blockIdx.x, b = blockIdx.y, tid = threadIdx.x;
    if (tid < 16) red[tid] = 0.f;
    // t1: wires (5,6,7,8,9) = l bits (10,9,8,7,6): [U6+CRX(5,6)]..[U9+CRX(8,9)]
    {
        float2 a[32]; int base = expand5<6,7,8,9,10>(tid);  // tid[5:0]->l[5:0], tid6->l11
#pragma unroll
        for (int i = 0; i < 32; i++) {
            int l = base | (((i>>4)&1)<<10) | (((i>>3)&1)<<9) | (((i>>2)&1)<<8)
                         | (((i>>1)&1)<<7) | ((i&1)<<6);
            a[i] = g_state[b][mapC(l, slab)];
        }
        apU32c<3,4>(a, g_U2[b][6], g_U2p[b][6]);
        apU32c<2,3>(a, g_U2[b][7], g_U2p[b][7]);
        apU32c<1,2>(a, g_U2[b][8], g_U2p[b][8]);
        apU32c<0,1>(a, g_U2[b][9], g_U2p[b][9]);
        sst32<10,9,8,7,6>(st, base, a);
    }
    __syncthreads();
    // t2: wires (9,10,11,12,13) = l bits (6,5,4,3,2): [U10+CRX(9,10)]..[U13+CRX(12,13)]
    {
        float2 a[32]; int base = expand5<2,3,4,5,6>(tid);
        sld32<6,5,4,3,2>(st, base, a);
        apU32c<3,4>(a, g_U2[b][10], g_U2p[b][10]);
        apU32c<2,3>(a, g_U2[b][11], g_U2p[b][11]);
        apU32c<1,2>(a, g_U2[b][12], g_U2p[b][12]);
        apU32c<0,1>(a, g_U2[b][13], g_U2p[b][13]);
        sst32<6,5,4,3,2>(st, base, a);
    }
    __syncthreads();
    // t3: b4=wire0(l11), b3=wire12(l3,inert), b2=wire13(l2), b1=wire14(l1), b0=wire15(l0)
    // [U14+CRX(13,14)]; [U15+CRX(14,15)]; CRX(15,0); measure
    {
        float2 a[32]; int base = expand5<0,1,2,3,11>(tid);  // tid[6:0] -> l[10:4]
        sld32<11,3,2,1,0>(st, base, a);
        apU32c<1,2>(a, g_U2[b][14], g_U2p[b][14]);          // ctrl b2 = wire13
        apU32c<0,1>(a, g_U2[b][15], g_U2p[b][15]);          // ctrl b1 = wire14
        crx32<0,4>(a, g_crx2[15]);                          // CRX(15,0): ctrl b0, tgt b4
        float p[32];
#pragma unroll
        for (int i = 0; i < 32; i++) p[i] = a[i].x*a[i].x + a[i].y*a[i].y;
        float T = 0.f, S0 = 0.f, S12 = 0.f, S13 = 0.f, S14 = 0.f, S15 = 0.f;
#pragma unroll
        for (int i = 0; i < 32; i++) {
            T += p[i];
            if (!((i >> 4) & 1)) S0  += p[i];
            if (!((i >> 3) & 1)) S12 += p[i];
            if (!((i >> 2) & 1)) S13 += p[i];
            if (!((i >> 1) & 1)) S14 += p[i];
            if (!(i & 1))        S15 += p[i];
        }
        float z[16];
        z[0]  = 2.f*S0  - T;
        z[12] = 2.f*S12 - T;
        z[13] = 2.f*S13 - T;
        z[14] = 2.f*S14 - T;
        z[15] = 2.f*S15 - T;
#pragma unroll
        for (int w = 1; w <= 4; w++)  z[w] = ((slab >> (4 - w)) & 1) ? -T : T;
#pragma unroll
        for (int w = 5; w <= 11; w++) z[w] = ((base >> (15 - w)) & 1) ? -T : T;
#pragma unroll
        for (int w = 0; w < 16; w++) {
#pragma unroll
            for (int o = 16; o > 0; o >>= 1) z[w] += __shfl_xor_sync(0xFFFFFFFFu, z[w], o);
        }
        if ((tid & 31) == 0)
#pragma unroll
            for (int w = 0; w < 16; w++) atomicAdd(&red[w], z[w]);
    }
    __syncthreads();
    if (tid < 16) atomicAdd(&g_feats[b][tid], red[tid]);
}

// ---------------- FC + log_softmax ----------------
__global__ void k_fc(const float* __restrict__ fc_w, const float* __restrict__ fc_b,
                     float* __restrict__ out) {
    int b = threadIdx.x;
    if (b >= BATCH) return;
    float f[16];
#pragma unroll
    for (int w = 0; w < 16; w++) f[w] = g_feats[b][w];
    float l[NCLS], m = -1e30f;
    for (int c = 0; c < NCLS; c++) {
        float s = fc_b[c];
#pragma unroll
        for (int w = 0; w < 16; w++) s += f[w] * fc_w[c * 16 + w];
        l[c] = s; m = fmaxf(m, s);
    }
    float se = 0.f;
    for (int c = 0; c < NCLS; c++) se += expf(l[c] - m);
    float lse = m + logf(se);
    for (int c = 0; c < NCLS; c++) out[b * NCLS + c] = l[c] - lse;
}

extern "C" void kernel_launch(void* const* d_in, const int* in_sizes, int n_in,
                              void* d_out, int out_size) {
    const float* x    = (const float*)d_in[0];
    const float* w0   = (const float*)d_in[1];
    const float* x0   = (const float*)d_in[2];
    const float* w1   = (const float*)d_in[3];
    const float* x1   = (const float*)d_in[4];
    const float* fc_w = (const float*)d_in[5];
    const float* fc_b = (const float*)d_in[6];
    float* out = (float*)d_out;

    k_prep<<<64, 16>>>(x, w0, x0, w1, x1);
    dim3 grid(16, BATCH);
    k_pass1<<<grid, 128>>>();
    k_passB<<<grid, 128>>>();
    k_passC<<<grid, 128>>>();
    k_fc<<<1, 64>>>(fc_w, fc_b, out);
}